// round 16
// baseline (speedup 1.0000x reference)
#include <cuda_runtime.h>
#include <math.h>

typedef unsigned long long u64;

#define T_LEN   1000000
#define S_LEN    999999          // RK4 steps
#define LCH      31              // steps per chunk
#define NB1      128
#define BLK      256
#define C1       (NB1*BLK)       // 32768 chunks
#define NB2      512             // phaseD: one thread per HALF-chunk
#define BLK2     128

// ---- k_setup smem: pool + transposed pool + fp32 A-power scratch ----
#define OFF0_POOL  0             // 101*144 = 14544
#define OFF0_POOLT 14544         // 14544
#define OFF0_A2    29088         // 144
#define OFF0_A3    29232         // 144
#define OFF0_A4    29376         // 144
#define K0_FLOATS  29520         // 118080 B

// ---- phaseB smem ----
#define OFF1_TO   0              // 7937 -> 7940
#define OFF1_U    7940           // 384
#define OFF1_U16  8324           // 204 -> 8528
#define OFF1_SA   8528           // 720
#define OFF1_VC   9248           // 12
#define OFF1_VC16 9260           // 12 -> 9272
#define K1_FLOATS 9272

// ---- scan23 smem ----
#define OFF3_SB   0              // 720
#define OFF3_SC   720            // 720
#define OFF3_GA   1440           // 384
#define OFF3_GP   1824           // 384
#define OFF3_TB   2208           // 32*145 = 4640 -> 6848
#define K3_FLOATS 6848

// ---- phaseD smem (half-chunk threads; 64 chunks/block -> To slab 1985) ----
#define OFFD_TO    0             // 1985 -> 1988
#define OFFD_TA    1988          // 32*145 = 4640 -> 6628
#define OFFD_M     6628          // 144
#define OFFD_M16   6772          // 144
#define OFFD_PT    6916          // 12
#define OFFD_QT    6928          // 12
#define OFFD_V     6940          // 12 -> 6952
#define OFFD_STAGE 6952          // 4 warps * 32 * 52 = 6656
#define KD_FLOATS  (OFFD_STAGE + 6656)    // 13608 floats = 54432 B

// ---------------- global scratch ----------------
__device__ float4 g_PW [C1*3];       // per-chunk within-warp inclusive prefixes
__device__ float4 g_F16[C1*3];       // per-chunk 16-step forcing prefix
__device__ float4 g_A  [1024*3];     // warp aggregates
__device__ float4 g_E  [1024*3];     // inclusive warp prefixes
__device__ float g_Mrow[144];        // M row-major
__device__ float g_M16row[144];      // M^16 row-major
__device__ float g_ptv[12], g_qtv[12], g_vv[12];
__device__ float g_U[32*12];
__device__ float g_U16[17*12];
__device__ float g_vc[12];
__device__ float g_vc16[12];
__device__ float g_TabArow[32*144];  // M^(31*(j+1)), ROW-major
__device__ float g_TabBrow[32*144];  // M^(992*(j+1)), ROW-major
__device__ float g_SCrow[5*144];     // M^(31744*2^k), ROW-major

// product triples (dst,a,b) into pool, grouped in rounds — constant memory.
// INVARIANT: within a round, all sources come from strictly earlier rounds.
__constant__ unsigned char tripD[99] = {
    2, 3,4, 5,6,7,8, 9,10,11,12,13,14,15,16,
    17,18,19,20,21,22,23,24,25,26,27,28,29,30,31,
    32, 33, 34,35, 36,37,38,39, 40,41,42,43,44,45,46,47,
    48,49,50,51,52,53,54,55,56,57,58,59,60,61,62,63,
    64, 65, 66,67, 68,69,70,71, 72,73,74,75,76,77,78,79,
    80,81,82,83,84,85,86,87,88,89,90,91,92,93,94,95,
    96, 97, 98, 99, 100 };
__constant__ unsigned char tripA[99] = {
    1, 2,2, 4,4,4,4, 8,8,8,8,8,8,8,8,
    16,16,16,16,16,16,16,16,16,16,16,16,16,16,16,
    31, 32, 33,33, 35,35,35,35, 39,39,39,39,39,39,39,39,
    47,47,47,47,47,47,47,47,47,47,47,47,47,47,47,47,
    63, 64, 65,65, 67,67,67,67, 71,71,71,71,71,71,71,71,
    79,79,79,79,79,79,79,79,79,79,79,79,79,79,79,79,
    95, 96, 97, 98, 99 };
__constant__ unsigned char tripB[99] = {
    1, 1,2, 1,2,3,4, 1,2,3,4,5,6,7,8,
    1,2,3,4,5,6,7,8,9,10,11,12,13,14,15,
    0, 32, 32,33, 32,33,34,35, 32,33,34,35,36,37,38,39,
    32,33,34,35,36,37,38,39,40,41,42,43,44,45,46,47,
    0, 64, 64,65, 64,65,66,67, 64,65,66,67,68,69,70,71,
    64,65,66,67,68,69,70,71,72,73,74,75,76,77,78,79,
    0, 96, 97, 98, 99 };
__constant__ short rndOff[23] = {0,1,3,7,15,30,31,32,34,38,46,62,63,64,66,70,78,94,95,96,97,98,99};

// ---------------- helpers ----------------
__device__ __forceinline__ void ld12(float* s, const float4* p) {
    float4 a = p[0], b = p[1], c = p[2];
    s[0]=a.x; s[1]=a.y; s[2]=a.z; s[3]=a.w;
    s[4]=b.x; s[5]=b.y; s[6]=b.z; s[7]=b.w;
    s[8]=c.x; s[9]=c.y; s[10]=c.z; s[11]=c.w;
}
__device__ __forceinline__ void st12(float4* p, const float* s) {
    p[0] = make_float4(s[0],s[1],s[2],s[3]);
    p[1] = make_float4(s[4],s[5],s[6],s[7]);
    p[2] = make_float4(s[8],s[9],s[10],s[11]);
}
__device__ __forceinline__ void mv_acc(float* s, const float* M, const float* o) {
    #pragma unroll
    for (int j = 0; j < 12; j++) {
        float oj = o[j];
        #pragma unroll
        for (int r = 0; r < 12; r++) s[r] = fmaf(M[j*12+r], oj, s[r]);
    }
}
__device__ __forceinline__ void warpscan12(float* s, const float* sMat, int lane) {
    #pragma unroll
    for (int k = 0; k < 5; k++) {
        int d = 1 << k;
        float o[12];
        #pragma unroll
        for (int r = 0; r < 12; r++) o[r] = __shfl_up_sync(0xffffffffu, s[r], d);
        if (lane >= d) mv_acc(s, sMat + k*144, o);
    }
}
__device__ __forceinline__ u64 f2pack(float lo, float hi) {
    u64 r; asm("mov.b64 %0, {%1,%2};" : "=l"(r) : "f"(lo), "f"(hi)); return r;
}
__device__ __forceinline__ void f2unpack(float& lo, float& hi, u64 v) {
    asm("mov.b64 {%0,%1}, %2;" : "=f"(lo), "=f"(hi) : "l"(v));
}
__device__ __forceinline__ u64 ffma2(u64 a, u64 b, u64 c) {
    u64 d; asm("fma.rn.f32x2 %0, %1, %2, %3;" : "=l"(d) : "l"(a), "l"(b), "l"(c)); return d;
}

// ================= K0: setup (1 block x 1024 threads, dual-pool) =================
__global__ void __launch_bounds__(1024) k_setup(
    const float* __restrict__ t_eval, const float* __restrict__ A,
    const float* __restrict__ B,      const float* __restrict__ loads_raw,
    const float* __restrict__ room_areas)
{
    extern __shared__ float smemF[];
    float* sPool  = smemF + OFF0_POOL;    // row-major matrices
    float* sPoolT = smemF + OFF0_POOLT;   // transposed copies
    float* fA2    = smemF + OFF0_A2;
    float* fA3    = smemF + OFF0_A3;
    float* fA4    = smemF + OFF0_A4;

    __shared__ double shQw[10], shb0[12], shBq[12], shh;
    __shared__ double sdpv[12], sdqv[12], sdvv[12];
    __shared__ float sTsum[144], sTsum16[144];
    const int t = threadIdx.x;

    if (t == 0) shh = (double)t_eval[1] - (double)t_eval[0];
    if (t < 10) {
        double x = (double)loads_raw[10 + t];    // gain row (action = 0)
        shQw[t] = 1.0 / (1.0 + exp(-x)) * 50.0 * (double)room_areas[t];
    }
    __syncthreads();
    if (t < 12) {
        shb0[t] = (double)B[t*11];
        double s = 0.0;
        #pragma unroll
        for (int j = 0; j < 10; j++) s += (double)B[t*11 + 1 + j] * shQw[j];
        shBq[t] = s;
    }
    // fp32 A powers (contribution to M < 5e-8 relative)
    if (t < 144) {
        int r = t/12, cc = t - (t/12)*12;
        float s = 0.f;
        #pragma unroll
        for (int j = 0; j < 12; j++) s = fmaf(__ldg(&A[r*12+j]), __ldg(&A[j*12+cc]), s);
        fA2[t] = s;
    }
    __syncthreads();
    if (t < 144) {
        int r = t/12, cc = t - (t/12)*12;
        float s3 = 0.f, s4 = 0.f;
        #pragma unroll
        for (int j = 0; j < 12; j++) {
            s3 = fmaf(fA2[r*12+j], __ldg(&A[j*12+cc]), s3);
            s4 = fmaf(fA2[r*12+j], fA2[j*12+cc], s4);
        }
        fA3[t] = s3; fA4[t] = s4;
    }
    __syncthreads();

    double h = shh, h2=h*h, h3=h2*h, h4=h3*h;
    if (t < 144) {
        int r=t/12, cc=t - (t/12)*12;
        double m = (r==cc?1.0:0.0) + h*(double)A[t] + h2/2.0*(double)fA2[t]
                 + h3/6.0*(double)fA3[t] + h4/24.0*(double)fA4[t];
        float mf = (float)m;
        float id = (r==cc) ? 1.0f : 0.0f;
        sPool [1*144 + t] = mf;
        sPoolT[1*144 + cc*12 + r] = mf;
        sPool [0*144 + t] = id;
        sPoolT[0*144 + t] = id;
        g_Mrow[t] = mf;
    }
    if (t < 12) {
        int r = t;
        double ab0=0,a2b0=0,a3b0=0,abq=0,a2bq=0,a3bq=0;
        #pragma unroll
        for (int k = 0; k < 12; k++) {
            double a1 = (double)A[r*12+k], a2 = (double)fA2[r*12+k], a3 = (double)fA3[r*12+k];
            ab0 += a1*shb0[k]; a2b0 += a2*shb0[k]; a3b0 += a3*shb0[k];
            abq += a1*shBq[k]; a2bq += a2*shBq[k]; a3bq += a3*shBq[k];
        }
        double pt = h/2.0*shb0[r] + h2/3.0*ab0 + h3/8.0*a2b0 + h4/24.0*a3b0;
        double qt = h/2.0*shb0[r] + h2/6.0*ab0 + h3/24.0*a2b0;
        double vv = h*shBq[r] + h2/2.0*abq + h3/6.0*a2bq + h4/24.0*a3bq;
        sdpv[r]=pt; sdqv[r]=qt; sdvv[r]=vv;
        g_ptv[r]=(float)pt; g_qtv[r]=(float)qt; g_vv[r]=(float)vv;
    }
    __syncthreads();

    // power pool: vectorized dual-pool products; barrier only BETWEEN rounds
    const int pid = t / 144;               // 0..7 (pid 7 idle)
    const int e   = t - pid*144;
    const int rr  = e / 12;
    const int ccx = e - rr*12;
    #pragma unroll 1
    for (int rd = 0; rd < 22; rd++) {
        const int s0 = rndOff[rd], s1 = rndOff[rd+1];
        #pragma unroll 1
        for (int base = s0; base < s1; base += 7) {
            const int k = base + pid;
            if (pid < 7 && k < s1) {
                const float4* a4 = (const float4*)(sPool  + (int)tripA[k]*144 + rr*12);
                const float4* b4 = (const float4*)(sPoolT + (int)tripB[k]*144 + ccx*12);
                float4 a0 = a4[0], a1 = a4[1], a2 = a4[2];
                float4 b0 = b4[0], b1 = b4[1], b2 = b4[2];
                float acc;
                acc = a0.x*b0.x;
                acc = fmaf(a0.y, b0.y, acc);
                acc = fmaf(a0.z, b0.z, acc);
                acc = fmaf(a0.w, b0.w, acc);
                acc = fmaf(a1.x, b1.x, acc);
                acc = fmaf(a1.y, b1.y, acc);
                acc = fmaf(a1.z, b1.z, acc);
                acc = fmaf(a1.w, b1.w, acc);
                acc = fmaf(a2.x, b2.x, acc);
                acc = fmaf(a2.y, b2.y, acc);
                acc = fmaf(a2.z, b2.z, acc);
                acc = fmaf(a2.w, b2.w, acc);
                int d = (int)tripD[k];
                sPool [d*144 + e] = acc;
                sPoolT[d*144 + ccx*12 + rr] = acc;
            }
        }
        __syncthreads();
    }

    // conv coefficients (31-step): u_i = M^(30-i) p (i<=30) + M^(31-i) q (i>=1)
    if (t < 384) {
        int i = t / 12, r = t - i*12;
        double s = 0.0;
        if (i <= 30) {
            const float* m = sPool + (30 - i)*144;
            #pragma unroll
            for (int j = 0; j < 12; j++) s += (double)m[r*12+j] * sdpv[j];
        }
        if (i >= 1) {
            const float* m = sPool + (31 - i)*144;
            #pragma unroll
            for (int j = 0; j < 12; j++) s += (double)m[r*12+j] * sdqv[j];
        }
        g_U[i*12 + r] = (float)s;
    }
    // 16-step conv coefficients: u16_i = M^(15-i) p (i<=15) + M^(16-i) q (i>=1), i=0..16
    if (t >= 512 && t < 512 + 204) {
        int tt = t - 512;
        int i = tt / 12, r = tt - i*12;
        double s = 0.0;
        if (i <= 15) {
            const float* m = sPool + (15 - i)*144;
            #pragma unroll
            for (int j = 0; j < 12; j++) s += (double)m[r*12+j] * sdpv[j];
        }
        if (i >= 1) {
            const float* m = sPool + (16 - i)*144;
            #pragma unroll
            for (int j = 0; j < 12; j++) s += (double)m[r*12+j] * sdqv[j];
        }
        g_U16[i*12 + r] = (float)s;
    }
    if (t < 144) {
        float s = 0.f, s16 = 0.f;
        for (int j = 0; j <= 30; j++) {
            s += sPool[j*144 + t];
            if (j <= 15) s16 += sPool[j*144 + t];
        }
        sTsum[t] = s; sTsum16[t] = s16;
    }
    __syncthreads();
    if (t < 12) {
        double s = 0.0, s16 = 0.0;
        #pragma unroll
        for (int k = 0; k < 12; k++) {
            s   += (double)sTsum  [t*12 + k] * sdvv[k];
            s16 += (double)sTsum16[t*12 + k] * sdvv[k];
        }
        g_vc[t] = (float)s;
        g_vc16[t] = (float)s16;
    }
    // ROW-major coalesced exports (consumers transpose into smem)
    for (int idx = t; idx < 32*144; idx += 1024) {
        g_TabArow[idx] = sPool[32*144 + idx];
        g_TabBrow[idx] = sPool[64*144 + idx];
    }
    if (t < 5*144) g_SCrow[t] = sPool[96*144 + t];
    if (t < 144) g_M16row[t] = sPool[16*144 + t];
}

// ================= K1: phaseB (conv + warp scan + F16) =================
__global__ void __launch_bounds__(BLK) k_phaseB(
    const float* __restrict__ Tout, const float* __restrict__ x0)
{
    extern __shared__ float smemF[];
    float* sTo  = smemF + OFF1_TO;
    float* sU   = smemF + OFF1_U;
    float* sU16 = smemF + OFF1_U16;
    float* sSA  = smemF + OFF1_SA;
    float* sVc  = smemF + OFF1_VC;
    float* sVc16= smemF + OFF1_VC16;

    const int tid  = threadIdx.x;
    const int lane = tid & 31;
    const int c = blockIdx.x * BLK + tid;
    const int wg = c >> 5;

    for (int i = tid; i < 384; i += BLK) sU[i] = g_U[i];
    for (int i = tid; i < 204; i += BLK) sU16[i] = g_U16[i];
    for (int i = tid; i < 5*144; i += BLK) {     // transpose on load -> col-major
        int k = i / 144, e = i - k*144, r = e/12, cc = e - (e/12)*12;
        sSA[k*144 + cc*12 + r] = g_TabArow[((1<<k) - 1)*144 + e];
    }
    if (tid < 12) { sVc[tid] = g_vc[tid]; sVc16[tid] = g_vc16[tid]; }
    {
        int base = blockIdx.x * (BLK*LCH);
        for (int i = tid; i < BLK*LCH + 1; i += BLK) {
            int gi = base + i; if (gi > T_LEN-1) gi = T_LEN-1;
            sTo[i] = Tout[gi];
        }
    }
    __syncthreads();

    const int off = tid * LCH;
    // 16-step forcing prefix F16 (independent of scan)
    {
        float f16[12];
        #pragma unroll
        for (int r = 0; r < 12; r++) f16[r] = sVc16[r];
        #pragma unroll
        for (int i = 0; i <= 16; i++) {
            float to = sTo[off + i];
            #pragma unroll
            for (int r = 0; r < 12; r++) f16[r] = fmaf(sU16[i*12+r], to, f16[r]);
        }
        st12(&g_F16[c*3], f16);
    }

    float s[12];
    #pragma unroll
    for (int r = 0; r < 12; r++) s[r] = sVc[r];
    #pragma unroll
    for (int i = 0; i < 32; i++) {
        float to = sTo[off + i];
        #pragma unroll
        for (int r = 0; r < 12; r++) s[r] = fmaf(sU[i*12+r], to, s[r]);
    }
    if (c == 0) {                 // fold M^31 * x0 into chunk 0
        float xv[12];
        #pragma unroll
        for (int r = 0; r < 12; r++) xv[r] = x0[r];
        mv_acc(s, sSA, xv);
    }
    warpscan12(s, sSA, lane);
    st12(&g_PW[c*3], s);
    if (lane == 31) st12(&g_A[wg*3], s);
}

// ================= K2: fused upper-level scan (1 block, 1024 thr) =================
__global__ void __launch_bounds__(1024) k_scan23(void) {
    extern __shared__ float smemF[];
    float* sSB = smemF + OFF3_SB;
    float* sSC = smemF + OFF3_SC;
    float* sGA = smemF + OFF3_GA;
    float* sGP = smemF + OFF3_GP;
    float* sTB = smemF + OFF3_TB;     // padded stride 145

    const int tid  = threadIdx.x;
    const int lane = tid & 31;
    const int ws   = tid >> 5;

    for (int i = tid; i < 5*144; i += 1024) {    // transpose on load
        int k = i / 144, e = i - k*144, r = e/12, cc = e - (e/12)*12;
        sSB[k*144 + cc*12 + r] = g_TabBrow[((1<<k) - 1)*144 + e];
        sSC[k*144 + cc*12 + r] = g_SCrow[i];
    }
    for (int idx = tid; idx < 32*144; idx += 1024) {
        int j = idx / 144, e = idx - j*144, r = e/12, cc = e - (e/12)*12;
        sTB[j*145 + cc*12 + r] = g_TabBrow[idx];
    }
    __syncthreads();

    float p[12];
    ld12(p, &g_A[tid*3]);
    warpscan12(p, sSB, lane);
    if (lane == 31) {
        #pragma unroll
        for (int r = 0; r < 12; r++) sGA[ws*12+r] = p[r];
    }
    __syncthreads();
    if (ws == 0) {
        float s2[12];
        #pragma unroll
        for (int r = 0; r < 12; r++) s2[r] = sGA[lane*12+r];
        warpscan12(s2, sSC, lane);
        #pragma unroll
        for (int r = 0; r < 12; r++) sGP[lane*12+r] = s2[r];
    }
    __syncthreads();
    if (ws >= 1) {
        float gp[12];
        #pragma unroll
        for (int r = 0; r < 12; r++) gp[r] = sGP[(ws-1)*12+r];
        mv_acc(p, sTB + lane*145, gp);
    }
    st12(&g_E[tid*3], p);
}

// ================= K3: phaseD — one thread per HALF-chunk =================
__global__ void __launch_bounds__(BLK2, 3) k_phaseD(
    const float* __restrict__ Tout, const float* __restrict__ x0,
    float* __restrict__ outF)
{
    extern __shared__ float smemF[];
    float* sTo  = smemF + OFFD_TO;
    float* sTA  = smemF + OFFD_TA;    // padded stride 145
    float* sM   = smemF + OFFD_M;
    float* sM16 = smemF + OFFD_M16;
    float* sPt  = smemF + OFFD_PT;
    float* sQt  = smemF + OFFD_QT;
    float* sV   = smemF + OFFD_V;
    float* sStage = smemF + OFFD_STAGE;

    const int tid  = threadIdx.x;
    const int lane = tid & 31;
    const int warpSlot = tid >> 5;
    const int hc = blockIdx.x * BLK2 + tid;      // half-chunk id, 0..65535
    const int cpair = hc >> 1;                   // chunk id
    const int half = hc & 1;

    // To slab: 64 chunks per block -> 64*31+1 = 1985 floats
    {
        int base = (blockIdx.x * 64) * LCH;
        for (int i = tid; i < 64*LCH + 1; i += BLK2) {
            int gi = base + i; if (gi > T_LEN-1) gi = T_LEN-1;
            sTo[i] = Tout[gi];
        }
    }
    for (int idx = tid; idx < 32*144; idx += BLK2) {   // transpose on load
        int j = idx / 144, e = idx - j*144, r = e/12, cc = e - (e/12)*12;
        sTA[j*145 + cc*12 + r] = g_TabArow[idx];
    }
    for (int i = tid; i < 144; i += BLK2) {            // row -> col-major
        int r = i/12, cc = i - (i/12)*12;
        sM  [cc*12 + r] = g_Mrow[i];
        sM16[cc*12 + r] = g_M16row[i];
    }
    if (tid < 12) { sPt[tid]=g_ptv[tid]; sQt[tid]=g_qtv[tid]; sV[tid]=g_vv[tid]; }
    __syncthreads();

    // reconstruct chunk start state
    float st[12];
    if (cpair == 0) {
        #pragma unroll
        for (int r = 0; r < 12; r++) st[r] = x0[r];
        if (hc == 0) {
            float4* o4 = (float4*)outF;
            o4[0] = make_float4(st[0],st[1],st[2],st[3]);
            o4[1] = make_float4(st[4],st[5],st[6],st[7]);
            o4[2] = make_float4(st[8],st[9],st[10],st[11]);
        }
    } else {
        int cm1 = cpair - 1, lane1 = cm1 & 31, wg1 = cm1 >> 5;
        ld12(st, &g_PW[cm1*3]);
        if (wg1 >= 1) {
            float Ev[12];
            ld12(Ev, &g_E[(wg1-1)*3]);
            mv_acc(st, sTA + lane1*145, Ev);
        }
    }
    // odd half: x_mid = M^16 * x_start + F16
    if (half) {
        float f16[12];
        ld12(f16, &g_F16[cpair*3]);
        mv_acc(f16, sM16, st);
        #pragma unroll
        for (int r = 0; r < 12; r++) st[r] = f16[r];
    }

    // packed state + register-resident matrix/vectors
    u64 S[6];
    #pragma unroll
    for (int p2 = 0; p2 < 6; p2++) S[p2] = f2pack(st[2*p2], st[2*p2+1]);
    u64 Mr[72];
    #pragma unroll
    for (int i = 0; i < 72; i++) Mr[i] = ((const u64*)sM)[i];
    u64 Ptr[6], Qtr[6], Vr[6];
    #pragma unroll
    for (int i = 0; i < 6; i++) {
        Ptr[i] = ((const u64*)sPt)[i];
        Qtr[i] = ((const u64*)sQt)[i];
        Vr[i]  = ((const u64*)sV)[i];
    }

    float* row = sStage + warpSlot*(32*52) + lane*52;
    const float* wbase = sStage + warpSlot*(32*52);
    const int cWarp = (blockIdx.x * BLK2 + warpSlot*32) >> 1;   // first chunk of warp
    const int lc = tid >> 1;                                    // local chunk in block
    const int off = lc*LCH + half*16;                           // To offset
    const int nSteps = 16 - half;                               // 16 or 15

    float tot = sTo[off];
    #pragma unroll 1
    for (int tile = 0; tile < 4; tile++) {
        const int i0 = tile * 4;
        #pragma unroll
        for (int i = 0; i < 4; i++) {
            if (i0 + i < nSteps) {
                float ton = sTo[off + i0 + i + 1];
                u64 tot2 = f2pack(tot, tot), ton2 = f2pack(ton, ton);
                u64 NS[6];
                #pragma unroll
                for (int p2 = 0; p2 < 6; p2++)
                    NS[p2] = ffma2(Ptr[p2], tot2, ffma2(Qtr[p2], ton2, Vr[p2]));
                #pragma unroll
                for (int jp = 0; jp < 6; jp++) {
                    float xa, xb; f2unpack(xa, xb, S[jp]);
                    u64 xa2 = f2pack(xa, xa), xb2 = f2pack(xb, xb);
                    #pragma unroll
                    for (int p2 = 0; p2 < 6; p2++) NS[p2] = ffma2(Mr[(2*jp)*6+p2],   xa2, NS[p2]);
                    #pragma unroll
                    for (int p2 = 0; p2 < 6; p2++) NS[p2] = ffma2(Mr[(2*jp+1)*6+p2], xb2, NS[p2]);
                }
                #pragma unroll
                for (int p2 = 0; p2 < 6; p2++) S[p2] = NS[p2];
                tot = ton;
                float* dst = row + i*12;
                ((ulonglong2*)dst)[0] = make_ulonglong2(S[0], S[1]);
                *(ulonglong2*)(dst + 4) = make_ulonglong2(S[2], S[3]);
                *(ulonglong2*)(dst + 8) = make_ulonglong2(S[4], S[5]);
            }
        }
        __syncwarp();
        // flush: 32 half-chunk segments x 12 16B-units; incremental indexing
        {
            int seg = (lane >= 24) ? 2 : ((lane >= 12) ? 1 : 0);
            int w16 = lane - seg*12;
            #pragma unroll 1
            for (int u = 0; u < 12; u++) {
                int istep = (w16*11) >> 5;          // w16/3 for w16 in [0,12)
                int rem = w16 - istep*3;
                int stepIdx = i0 + istep;
                int segHalf = seg & 1;
                int segC = cWarp + (seg >> 1);
                int n1 = segC*LCH + segHalf*16 + stepIdx + 1;
                if (stepIdx < 16 - segHalf && n1 <= S_LEN) {
                    ulonglong2 v = *(const ulonglong2*)(wbase + seg*52 + w16*4);
                    *(ulonglong2*)(outF + n1*12 + rem*4) = v;
                }
                seg += 2; w16 += 8;
                if (w16 >= 12) { w16 -= 12; seg += 1; }
            }
        }
        __syncwarp();
    }
}

// ---------------- launch ----------------
extern "C" void kernel_launch(void* const* d_in, const int* in_sizes, int n_in,
                              void* d_out, int out_size) {
    const float* t_eval = (const float*)d_in[0];
    const float* x0     = (const float*)d_in[1];
    const float* A      = (const float*)d_in[2];
    const float* B      = (const float*)d_in[3];
    const float* Tout   = (const float*)d_in[4];
    const float* loads  = (const float*)d_in[5];
    const float* areas  = (const float*)d_in[6];
    float* outF = (float*)d_out;

    size_t smem0 = (size_t)K0_FLOATS * sizeof(float);
    size_t smem1 = (size_t)K1_FLOATS * sizeof(float);
    size_t smem3 = (size_t)K3_FLOATS * sizeof(float);
    size_t smem2 = (size_t)KD_FLOATS * sizeof(float);
    cudaFuncSetAttribute(k_setup,  cudaFuncAttributeMaxDynamicSharedMemorySize, (int)smem0);
    cudaFuncSetAttribute(k_phaseB, cudaFuncAttributeMaxDynamicSharedMemorySize, (int)smem1);
    cudaFuncSetAttribute(k_scan23, cudaFuncAttributeMaxDynamicSharedMemorySize, (int)smem3);
    cudaFuncSetAttribute(k_phaseD, cudaFuncAttributeMaxDynamicSharedMemorySize, (int)smem2);

    k_setup <<<1,   1024, smem0>>>(t_eval, A, B, loads, areas);
    k_phaseB<<<NB1, BLK,  smem1>>>(Tout, x0);
    k_scan23<<<1,   1024, smem3>>>();
    k_phaseD<<<NB2, BLK2, smem2>>>(Tout, x0, outF);
}

// round 17
// speedup vs baseline: 1.2639x; 1.2639x over previous
#include <cuda_runtime.h>
#include <math.h>

typedef unsigned long long u64;

#define T_LEN   1000000
#define S_LEN    999999          // RK4 steps
#define LCH      31              // steps per chunk
#define NB1      128
#define BLK      256
#define C1       (NB1*BLK)       // 32768 chunks
#define NB2      256
#define BLK2     128

// ---- k_setup smem: pool + transposed pool + fp32 A-power scratch ----
#define OFF0_POOL  0             // 101*144 = 14544
#define OFF0_POOLT 14544         // 14544
#define OFF0_A2    29088         // 144
#define OFF0_A3    29232         // 144
#define OFF0_A4    29376         // 144
#define K0_FLOATS  29520         // 118080 B

// ---- phaseB smem ----
#define OFF1_TO   0              // 7940 (vector-load slab)
#define OFF1_U    7940           // 384
#define OFF1_SA   8324           // 720
#define OFF1_VC   9044           // 12 -> 9056
#define K1_FLOATS 9056

// ---- scan23 smem ----
#define OFF3_SB   0              // 720
#define OFF3_SC   720            // 720
#define OFF3_GA   1440           // 384
#define OFF3_GP   1824           // 384
#define OFF3_TB   2208           // 32*145 = 4640 -> 6848
#define K3_FLOATS 6848

// ---- phaseD smem ----
#define OFFD_TO    0             // 3972 (vector-load slab)
#define OFFD_TA    3972          // 32*145 = 4640 -> 8612
#define OFFD_M     8612          // 144
#define OFFD_PT    8756          // 12
#define OFFD_QT    8768          // 12
#define OFFD_V     8780          // 12 -> 8792
#define OFFD_STAGE 8792          // 4 warps * 3200 = 12800
#define KD_FLOATS  (OFFD_STAGE + 12800)   // 21592 floats = 86368 B

// ---------------- global scratch ----------------
__device__ float4 g_PW[C1*3];        // per-chunk within-warp inclusive prefixes
__device__ float4 g_A [1024*3];      // warp aggregates
__device__ float4 g_E [1024*3];      // inclusive warp prefixes
__device__ float g_Mrow[144];        // M row-major
__device__ float g_ptv[12], g_qtv[12], g_vv[12];
__device__ float g_U[32*12];
__device__ float g_vc[12];
__device__ float g_TabArow[32*144];  // M^(31*(j+1)), ROW-major
__device__ float g_TabBrow[32*144];  // M^(992*(j+1)), ROW-major
__device__ float g_SCrow[5*144];     // M^(31744*2^k), ROW-major

// product triples (dst,a,b) into pool, grouped in rounds — constant memory.
// Copy-rounds merged into their successors: slot 33 = 31*31 (not 32*32),
// 65 = 63*63, 97 = 95*95 — bitwise-identical since 32/64/96 are copies.
// INVARIANT: within a round, all sources come from strictly earlier rounds.
__constant__ unsigned char tripD[99] = {
    2, 3,4, 5,6,7,8, 9,10,11,12,13,14,15,16,
    17,18,19,20,21,22,23,24,25,26,27,28,29,30,31,
    32, 33, 34,35, 36,37,38,39, 40,41,42,43,44,45,46,47,
    48,49,50,51,52,53,54,55,56,57,58,59,60,61,62,63,
    64, 65, 66,67, 68,69,70,71, 72,73,74,75,76,77,78,79,
    80,81,82,83,84,85,86,87,88,89,90,91,92,93,94,95,
    96, 97, 98, 99, 100 };
__constant__ unsigned char tripA[99] = {
    1, 2,2, 4,4,4,4, 8,8,8,8,8,8,8,8,
    16,16,16,16,16,16,16,16,16,16,16,16,16,16,16,
    31, 31, 33,33, 35,35,35,35, 39,39,39,39,39,39,39,39,
    47,47,47,47,47,47,47,47,47,47,47,47,47,47,47,47,
    63, 63, 65,65, 67,67,67,67, 71,71,71,71,71,71,71,71,
    79,79,79,79,79,79,79,79,79,79,79,79,79,79,79,79,
    95, 95, 97, 98, 99 };
__constant__ unsigned char tripB[99] = {
    1, 1,2, 1,2,3,4, 1,2,3,4,5,6,7,8,
    1,2,3,4,5,6,7,8,9,10,11,12,13,14,15,
    0, 31, 32,33, 32,33,34,35, 32,33,34,35,36,37,38,39,
    32,33,34,35,36,37,38,39,40,41,42,43,44,45,46,47,
    0, 63, 64,65, 64,65,66,67, 64,65,66,67,68,69,70,71,
    64,65,66,67,68,69,70,71,72,73,74,75,76,77,78,79,
    0, 95, 97, 98, 99 };
__constant__ short rndOff[20] = {0,1,3,7,15,30,32,34,38,46,62,64,66,70,78,94,96,97,98,99};

// ---------------- helpers ----------------
__device__ __forceinline__ void ld12(float* s, const float4* p) {
    float4 a = p[0], b = p[1], c = p[2];
    s[0]=a.x; s[1]=a.y; s[2]=a.z; s[3]=a.w;
    s[4]=b.x; s[5]=b.y; s[6]=b.z; s[7]=b.w;
    s[8]=c.x; s[9]=c.y; s[10]=c.z; s[11]=c.w;
}
__device__ __forceinline__ void st12(float4* p, const float* s) {
    p[0] = make_float4(s[0],s[1],s[2],s[3]);
    p[1] = make_float4(s[4],s[5],s[6],s[7]);
    p[2] = make_float4(s[8],s[9],s[10],s[11]);
}
__device__ __forceinline__ void mv_acc(float* s, const float* M, const float* o) {
    #pragma unroll
    for (int j = 0; j < 12; j++) {
        float oj = o[j];
        #pragma unroll
        for (int r = 0; r < 12; r++) s[r] = fmaf(M[j*12+r], oj, s[r]);
    }
}
__device__ __forceinline__ void warpscan12(float* s, const float* sMat, int lane) {
    #pragma unroll
    for (int k = 0; k < 5; k++) {
        int d = 1 << k;
        float o[12];
        #pragma unroll
        for (int r = 0; r < 12; r++) o[r] = __shfl_up_sync(0xffffffffu, s[r], d);
        if (lane >= d) mv_acc(s, sMat + k*144, o);
    }
}
__device__ __forceinline__ u64 f2pack(float lo, float hi) {
    u64 r; asm("mov.b64 %0, {%1,%2};" : "=l"(r) : "f"(lo), "f"(hi)); return r;
}
__device__ __forceinline__ void f2unpack(float& lo, float& hi, u64 v) {
    asm("mov.b64 {%0,%1}, %2;" : "=f"(lo), "=f"(hi) : "l"(v));
}
__device__ __forceinline__ u64 ffma2(u64 a, u64 b, u64 c) {
    u64 d; asm("fma.rn.f32x2 %0, %1, %2, %3;" : "=l"(d) : "l"(a), "l"(b), "l"(c)); return d;
}

// ================= K0: setup (1 block x 1024 threads, dual-pool) =================
__global__ void __launch_bounds__(1024) k_setup(
    const float* __restrict__ t_eval, const float* __restrict__ A,
    const float* __restrict__ B,      const float* __restrict__ loads_raw,
    const float* __restrict__ room_areas)
{
    extern __shared__ float smemF[];
    float* sPool  = smemF + OFF0_POOL;    // row-major matrices
    float* sPoolT = smemF + OFF0_POOLT;   // transposed copies
    float* fA2    = smemF + OFF0_A2;
    float* fA3    = smemF + OFF0_A3;
    float* fA4    = smemF + OFF0_A4;

    __shared__ double shQw[10], shb0[12], shBq[12], shh;
    __shared__ double sdpv[12], sdqv[12], sdvv[12];
    __shared__ float sTsum[144];
    const int t = threadIdx.x;

    if (t == 0) shh = (double)t_eval[1] - (double)t_eval[0];
    if (t < 10) {
        double x = (double)loads_raw[10 + t];    // gain row (action = 0)
        shQw[t] = 1.0 / (1.0 + exp(-x)) * 50.0 * (double)room_areas[t];
    }
    __syncthreads();
    if (t < 12) {
        shb0[t] = (double)B[t*11];
        double s = 0.0;
        #pragma unroll
        for (int j = 0; j < 10; j++) s += (double)B[t*11 + 1 + j] * shQw[j];
        shBq[t] = s;
    }
    // fp32 A powers (contribution to M < 5e-8 relative)
    if (t < 144) {
        int r = t/12, cc = t - (t/12)*12;
        float s = 0.f;
        #pragma unroll
        for (int j = 0; j < 12; j++) s = fmaf(__ldg(&A[r*12+j]), __ldg(&A[j*12+cc]), s);
        fA2[t] = s;
    }
    __syncthreads();
    if (t < 144) {
        int r = t/12, cc = t - (t/12)*12;
        float s3 = 0.f, s4 = 0.f;
        #pragma unroll
        for (int j = 0; j < 12; j++) {
            s3 = fmaf(fA2[r*12+j], __ldg(&A[j*12+cc]), s3);
            s4 = fmaf(fA2[r*12+j], fA2[j*12+cc], s4);
        }
        fA3[t] = s3; fA4[t] = s4;
    }
    __syncthreads();

    double h = shh, h2=h*h, h3=h2*h, h4=h3*h;
    if (t < 144) {
        int r=t/12, cc=t - (t/12)*12;
        double m = (r==cc?1.0:0.0) + h*(double)A[t] + h2/2.0*(double)fA2[t]
                 + h3/6.0*(double)fA3[t] + h4/24.0*(double)fA4[t];
        float mf = (float)m;
        float id = (r==cc) ? 1.0f : 0.0f;
        sPool [1*144 + t] = mf;
        sPoolT[1*144 + cc*12 + r] = mf;
        sPool [0*144 + t] = id;
        sPoolT[0*144 + t] = id;
        g_Mrow[t] = mf;
    }
    if (t < 12) {
        int r = t;
        double ab0=0,a2b0=0,a3b0=0,abq=0,a2bq=0,a3bq=0;
        #pragma unroll
        for (int k = 0; k < 12; k++) {
            double a1 = (double)A[r*12+k], a2 = (double)fA2[r*12+k], a3 = (double)fA3[r*12+k];
            ab0 += a1*shb0[k]; a2b0 += a2*shb0[k]; a3b0 += a3*shb0[k];
            abq += a1*shBq[k]; a2bq += a2*shBq[k]; a3bq += a3*shBq[k];
        }
        double pt = h/2.0*shb0[r] + h2/3.0*ab0 + h3/8.0*a2b0 + h4/24.0*a3b0;
        double qt = h/2.0*shb0[r] + h2/6.0*ab0 + h3/24.0*a2b0;
        double vv = h*shBq[r] + h2/2.0*abq + h3/6.0*a2bq + h4/24.0*a3bq;
        sdpv[r]=pt; sdqv[r]=qt; sdvv[r]=vv;
        g_ptv[r]=(float)pt; g_qtv[r]=(float)qt; g_vv[r]=(float)vv;
    }
    __syncthreads();

    // power pool: vectorized dual-pool products; barrier only BETWEEN rounds
    const int pid = t / 144;               // 0..7 (pid 7 idle)
    const int e   = t - pid*144;
    const int rr  = e / 12;
    const int ccx = e - rr*12;
    #pragma unroll 1
    for (int rd = 0; rd < 19; rd++) {
        const int s0 = rndOff[rd], s1 = rndOff[rd+1];
        #pragma unroll 1
        for (int base = s0; base < s1; base += 7) {
            const int k = base + pid;
            if (pid < 7 && k < s1) {
                const float4* a4 = (const float4*)(sPool  + (int)tripA[k]*144 + rr*12);
                const float4* b4 = (const float4*)(sPoolT + (int)tripB[k]*144 + ccx*12);
                float4 a0 = a4[0], a1 = a4[1], a2 = a4[2];
                float4 b0 = b4[0], b1 = b4[1], b2 = b4[2];
                float acc;
                acc = a0.x*b0.x;
                acc = fmaf(a0.y, b0.y, acc);
                acc = fmaf(a0.z, b0.z, acc);
                acc = fmaf(a0.w, b0.w, acc);
                acc = fmaf(a1.x, b1.x, acc);
                acc = fmaf(a1.y, b1.y, acc);
                acc = fmaf(a1.z, b1.z, acc);
                acc = fmaf(a1.w, b1.w, acc);
                acc = fmaf(a2.x, b2.x, acc);
                acc = fmaf(a2.y, b2.y, acc);
                acc = fmaf(a2.z, b2.z, acc);
                acc = fmaf(a2.w, b2.w, acc);
                int d = (int)tripD[k];
                sPool [d*144 + e] = acc;
                sPoolT[d*144 + ccx*12 + rr] = acc;
            }
        }
        __syncthreads();
    }

    // conv coefficients: u_i = M^(30-i) p (i<=30) + M^(31-i) q (i>=1)
    if (t < 384) {
        int i = t / 12, r = t - i*12;
        double s = 0.0;
        if (i <= 30) {
            const float* m = sPool + (30 - i)*144;
            #pragma unroll
            for (int j = 0; j < 12; j++) s += (double)m[r*12+j] * sdpv[j];
        }
        if (i >= 1) {
            const float* m = sPool + (31 - i)*144;
            #pragma unroll
            for (int j = 0; j < 12; j++) s += (double)m[r*12+j] * sdqv[j];
        }
        g_U[i*12 + r] = (float)s;
    }
    if (t < 144) {
        float s = 0.f;
        for (int j = 0; j <= 30; j++) s += sPool[j*144 + t];
        sTsum[t] = s;
    }
    __syncthreads();
    if (t < 12) {
        double s = 0.0;
        #pragma unroll
        for (int k = 0; k < 12; k++) s += (double)sTsum[t*12 + k] * sdvv[k];
        g_vc[t] = (float)s;
    }
    // ROW-major coalesced exports (consumers transpose into smem)
    for (int idx = t; idx < 32*144; idx += 1024) {
        g_TabArow[idx] = sPool[32*144 + idx];
        g_TabBrow[idx] = sPool[64*144 + idx];
    }
    if (t < 5*144) g_SCrow[t] = sPool[96*144 + t];
}

// ================= K1: phaseB (conv + warp scan) =================
__global__ void __launch_bounds__(BLK) k_phaseB(
    const float* __restrict__ Tout, const float* __restrict__ x0)
{
    extern __shared__ float smemF[];
    float* sTo = smemF + OFF1_TO;
    float* sU  = smemF + OFF1_U;
    float* sSA = smemF + OFF1_SA;
    float* sVc = smemF + OFF1_VC;

    const int tid  = threadIdx.x;
    const int lane = tid & 31;
    const int c = blockIdx.x * BLK + tid;
    const int wg = c >> 5;

    for (int i = tid; i < 384; i += BLK) sU[i] = g_U[i];
    for (int i = tid; i < 5*144; i += BLK) {     // transpose on load -> col-major
        int k = i / 144, e = i % 144, r = e/12, cc = e - (e/12)*12;
        sSA[k*144 + cc*12 + r] = g_TabArow[((1<<k) - 1)*144 + e];
    }
    if (tid < 12) sVc[tid] = g_vc[tid];
    {
        int base = blockIdx.x * (BLK*LCH);
        if (base + 1985*4 <= T_LEN) {            // vector path (1985 f4 = 7940 >= 7937)
            const float4* T4 = (const float4*)(Tout + base);
            float4* S4 = (float4*)sTo;
            for (int i = tid; i < 1985; i += BLK) S4[i] = T4[i];
        } else {
            for (int i = tid; i < BLK*LCH + 1; i += BLK) {
                int gi = base + i; if (gi > T_LEN-1) gi = T_LEN-1;
                sTo[i] = Tout[gi];
            }
        }
    }
    __syncthreads();

    float s[12];
    #pragma unroll
    for (int r = 0; r < 12; r++) s[r] = sVc[r];
    const int off = tid * LCH;
    #pragma unroll
    for (int i = 0; i < 32; i++) {
        float to = sTo[off + i];
        #pragma unroll
        for (int r = 0; r < 12; r++) s[r] = fmaf(sU[i*12+r], to, s[r]);
    }
    if (c == 0) {                 // fold M^31 * x0 into chunk 0
        float xv[12];
        #pragma unroll
        for (int r = 0; r < 12; r++) xv[r] = x0[r];
        mv_acc(s, sSA, xv);
    }
    warpscan12(s, sSA, lane);
    st12(&g_PW[c*3], s);
    if (lane == 31) st12(&g_A[wg*3], s);
}

// ================= K2: fused upper-level scan (1 block, 1024 thr) =================
__global__ void __launch_bounds__(1024) k_scan23(void) {
    extern __shared__ float smemF[];
    float* sSB = smemF + OFF3_SB;
    float* sSC = smemF + OFF3_SC;
    float* sGA = smemF + OFF3_GA;
    float* sGP = smemF + OFF3_GP;
    float* sTB = smemF + OFF3_TB;     // padded stride 145

    const int tid  = threadIdx.x;
    const int lane = tid & 31;
    const int ws   = tid >> 5;

    for (int i = tid; i < 5*144; i += 1024) {    // transpose on load
        int k = i / 144, e = i - k*144, r = e/12, cc = e - (e/12)*12;
        sSB[k*144 + cc*12 + r] = g_TabBrow[((1<<k) - 1)*144 + e];
        sSC[k*144 + cc*12 + r] = g_SCrow[i];
    }
    for (int idx = tid; idx < 32*144; idx += 1024) {
        int j = idx / 144, e = idx - j*144, r = e/12, cc = e - (e/12)*12;
        sTB[j*145 + cc*12 + r] = g_TabBrow[idx];
    }
    __syncthreads();

    float p[12];
    ld12(p, &g_A[tid*3]);
    warpscan12(p, sSB, lane);
    if (lane == 31) {
        #pragma unroll
        for (int r = 0; r < 12; r++) sGA[ws*12+r] = p[r];
    }
    __syncthreads();
    if (ws == 0) {
        float s2[12];
        #pragma unroll
        for (int r = 0; r < 12; r++) s2[r] = sGA[lane*12+r];
        warpscan12(s2, sSC, lane);
        #pragma unroll
        for (int r = 0; r < 12; r++) sGP[lane*12+r] = s2[r];
    }
    __syncthreads();
    if (ws >= 1) {
        float gp[12];
        #pragma unroll
        for (int r = 0; r < 12; r++) gp[r] = sGP[(ws-1)*12+r];
        mv_acc(p, sTB + lane*145, gp);
    }
    st12(&g_E[tid*3], p);
}

// ================= K3: phaseD (register-resident M, staged stores) =================
__global__ void __launch_bounds__(BLK2) k_phaseD(
    const float* __restrict__ Tout, const float* __restrict__ x0,
    float* __restrict__ outF)
{
    extern __shared__ float smemF[];
    float* sTo = smemF + OFFD_TO;
    float* sTA = smemF + OFFD_TA;     // padded stride 145
    float* sM  = smemF + OFFD_M;
    float* sPt = smemF + OFFD_PT;
    float* sQt = smemF + OFFD_QT;
    float* sV  = smemF + OFFD_V;
    float* sStage = smemF + OFFD_STAGE;

    const int tid  = threadIdx.x;
    const int lane = tid & 31;
    const int warpSlot = tid >> 5;
    const int c = blockIdx.x * BLK2 + tid;

    {
        int base = blockIdx.x * (BLK2*LCH);
        if (base + 993*4 <= T_LEN) {             // vector path (993 f4 = 3972 >= 3969)
            const float4* T4 = (const float4*)(Tout + base);
            float4* S4 = (float4*)sTo;
            for (int i = tid; i < 993; i += BLK2) S4[i] = T4[i];
        } else {
            for (int i = tid; i < BLK2*LCH + 1; i += BLK2) {
                int gi = base + i; if (gi > T_LEN-1) gi = T_LEN-1;
                sTo[i] = Tout[gi];
            }
        }
    }
    for (int idx = tid; idx < 32*144; idx += BLK2) {   // transpose on load
        int j = idx / 144, e = idx - j*144, r = e/12, cc = e - (e/12)*12;
        sTA[j*145 + cc*12 + r] = g_TabArow[idx];
    }
    for (int i = tid; i < 144; i += BLK2) {            // M row -> col-major
        int r = i/12, cc = i - (i/12)*12;
        sM[cc*12 + r] = g_Mrow[i];
    }
    if (tid < 12) { sPt[tid]=g_ptv[tid]; sQt[tid]=g_qtv[tid]; sV[tid]=g_vv[tid]; }
    __syncthreads();

    // reconstruct start state
    float st[12];
    if (c == 0) {
        #pragma unroll
        for (int r = 0; r < 12; r++) st[r] = x0[r];
        float4* o4 = (float4*)outF;
        o4[0] = make_float4(st[0],st[1],st[2],st[3]);
        o4[1] = make_float4(st[4],st[5],st[6],st[7]);
        o4[2] = make_float4(st[8],st[9],st[10],st[11]);
    } else {
        int cm1 = c - 1, lane1 = cm1 & 31, wg1 = cm1 >> 5;
        ld12(st, &g_PW[cm1*3]);
        if (wg1 >= 1) {
            float Ev[12];
            ld12(Ev, &g_E[(wg1-1)*3]);
            mv_acc(st, sTA + lane1*145, Ev);
        }
    }

    // packed state + register-resident matrix/vectors
    u64 S[6];
    #pragma unroll
    for (int p2 = 0; p2 < 6; p2++) S[p2] = f2pack(st[2*p2], st[2*p2+1]);
    u64 Mr[72];
    #pragma unroll
    for (int i = 0; i < 72; i++) Mr[i] = ((const u64*)sM)[i];
    u64 Ptr[6], Qtr[6], Vr[6];
    #pragma unroll
    for (int i = 0; i < 6; i++) {
        Ptr[i] = ((const u64*)sPt)[i];
        Qtr[i] = ((const u64*)sQt)[i];
        Vr[i]  = ((const u64*)sV)[i];
    }

    float* row = sStage + warpSlot*3200 + lane*100;
    const float* wbase = sStage + warpSlot*3200;
    const int nBase = (blockIdx.x*BLK2 + warpSlot*32) * LCH;
    const int off = tid * LCH;

    // flush index tables: w16 has period 3; precompute istep/rem/seg-deltas
    const int seg0 = (lane >= 24) ? 1 : 0;
    int wj[3], dj[3], isj[3], rmj[3];
    {
        int w = lane - seg0*24;
        #pragma unroll
        for (int j = 0; j < 3; j++) {
            wj[j]  = w;
            isj[j] = (w*11) >> 5;          // w/3 for w in [0,24)
            rmj[j] = w - isj[j]*3;
            int wn = w + 8;
            dj[j]  = (wn >= 24) ? 2 : 1;
            w      = (wn >= 24) ? wn - 24 : wn;
        }
    }

    float tot = sTo[off];
    #pragma unroll 1
    for (int tile = 0; tile < 4; tile++) {
        const int i0 = tile * 8;
        #pragma unroll
        for (int i = 0; i < 8; i++) {
            if (i0 + i < LCH) {
                float ton = sTo[off + i0 + i + 1];
                u64 tot2 = f2pack(tot, tot), ton2 = f2pack(ton, ton);
                u64 NS[6];
                #pragma unroll
                for (int p2 = 0; p2 < 6; p2++)
                    NS[p2] = ffma2(Ptr[p2], tot2, ffma2(Qtr[p2], ton2, Vr[p2]));
                #pragma unroll
                for (int jp = 0; jp < 6; jp++) {
                    float xa, xb; f2unpack(xa, xb, S[jp]);
                    u64 xa2 = f2pack(xa, xa), xb2 = f2pack(xb, xb);
                    #pragma unroll
                    for (int p2 = 0; p2 < 6; p2++) NS[p2] = ffma2(Mr[(2*jp)*6+p2],   xa2, NS[p2]);
                    #pragma unroll
                    for (int p2 = 0; p2 < 6; p2++) NS[p2] = ffma2(Mr[(2*jp+1)*6+p2], xb2, NS[p2]);
                }
                #pragma unroll
                for (int p2 = 0; p2 < 6; p2++) S[p2] = NS[p2];
                tot = ton;
                float* dst = row + i*12;
                ((ulonglong2*)dst)[0] = make_ulonglong2(S[0], S[1]);
                *(ulonglong2*)(dst + 4) = make_ulonglong2(S[2], S[3]);
                *(ulonglong2*)(dst + 8) = make_ulonglong2(S[4], S[5]);
            }
        }
        __syncwarp();
        // flush: 32 segments x 24 16B-units; period-3 hoisted indices
        {
            bool okj[3];
            int sidx[3];
            #pragma unroll
            for (int j = 0; j < 3; j++) {
                sidx[j] = i0 + isj[j];
                okj[j]  = (sidx[j] < LCH);
            }
            int segCur = seg0;
            #pragma unroll
            for (int u = 0; u < 24; u++) {
                const int j = u - (u/3)*3;     // u % 3, compile-time under unroll
                int n1 = nBase + segCur*LCH + sidx[j] + 1;
                if (okj[j] && n1 <= S_LEN) {
                    ulonglong2 v = *(const ulonglong2*)(wbase + segCur*100 + wj[j]*4);
                    *(ulonglong2*)(outF + n1*12 + rmj[j]*4) = v;
                }
                segCur += dj[j];
            }
        }
        __syncwarp();
    }
}

// ---------------- launch ----------------
extern "C" void kernel_launch(void* const* d_in, const int* in_sizes, int n_in,
                              void* d_out, int out_size) {
    const float* t_eval = (const float*)d_in[0];
    const float* x0     = (const float*)d_in[1];
    const float* A      = (const float*)d_in[2];
    const float* B      = (const float*)d_in[3];
    const float* Tout   = (const float*)d_in[4];
    const float* loads  = (const float*)d_in[5];
    const float* areas  = (const float*)d_in[6];
    float* outF = (float*)d_out;

    size_t smem0 = (size_t)K0_FLOATS * sizeof(float);
    size_t smem1 = (size_t)K1_FLOATS * sizeof(float);
    size_t smem3 = (size_t)K3_FLOATS * sizeof(float);
    size_t smem2 = (size_t)KD_FLOATS * sizeof(float);
    cudaFuncSetAttribute(k_setup,  cudaFuncAttributeMaxDynamicSharedMemorySize, (int)smem0);
    cudaFuncSetAttribute(k_phaseB, cudaFuncAttributeMaxDynamicSharedMemorySize, (int)smem1);
    cudaFuncSetAttribute(k_scan23, cudaFuncAttributeMaxDynamicSharedMemorySize, (int)smem3);
    cudaFuncSetAttribute(k_phaseD, cudaFuncAttributeMaxDynamicSharedMemorySize, (int)smem2);

    k_setup <<<1,   1024, smem0>>>(t_eval, A, B, loads, areas);
    k_phaseB<<<NB1, BLK,  smem1>>>(Tout, x0);
    k_scan23<<<1,   1024, smem3>>>();
    k_phaseD<<<NB2, BLK2, smem2>>>(Tout, x0, outF);
}